// round 6
// baseline (speedup 1.0000x reference)
#include <cuda_runtime.h>
#include <cstdint>

#define N_NODES 100000
#define N_EDGES 1600000
#define IN_DIM  256
#define HID_DIM 64
#define OUT_DIM 64

// -------- scratch (device globals: allocation-free per harness rules) --------
__device__ __align__(16) float g_ew[N_EDGES];          // normalized edge weights
__device__ __align__(16) float g_norm[N_EDGES];        // dinv[row]*ew*dinv[col]
__device__ __align__(16) float g_deg[N_NODES];         // degree (init 1.0 self-loop)
__device__ __align__(16) float g_dinv[N_NODES];        // deg^{-1/2}
__device__ __align__(16) float g_y1[N_NODES * HID_DIM];    // x @ W1
__device__ __align__(16) float g_agg1[N_NODES * HID_DIM];  // layer-1 aggregation
__device__ __align__(16) float g_y2[N_NODES * OUT_DIM];    // h @ W2
__device__ __align__(16) float g_agg2[N_NODES * OUT_DIM];  // layer-2 aggregation
__device__ int g_min, g_max;
__device__ int g_ei64, g_ec64;   // 1 if buffer really is int64, 0 if int32

// flag-selected integer load (handles JAX silently demoting int64 -> int32)
__device__ __forceinline__ long long ld_int(const void* p, long long i, int is64) {
    if (is64) return ((const long long*)p)[i];
    return (long long)((const int*)p)[i];
}

// ------------------------------- prep kernels -------------------------------
__global__ void k_init() {
    int i = blockIdx.x * blockDim.x + threadIdx.x;
    if (i < N_NODES) g_deg[i] = 1.0f;               // self-loop weight 1
    if (i == 0) {
        g_min = 0x7fffffff; g_max = (int)0x80000000;
        g_ei64 = 1; g_ec64 = 1;
    }
}

// Probe dtype: if ANY of the first 4096 int64-interpreted values is out of
// plausible range, the buffer is int32. (True int64 data always in-range;
// int32 data read as int64 is ~always >= 2^32.)
__global__ void k_detect(const void* ei, const void* ec) {
    int bad_ei = 0, bad_ec = 0;
    for (int i = threadIdx.x; i < 4096; i += blockDim.x) {
        long long v = ((const long long*)ei)[i];
        if (v < 0 || v >= N_NODES) bad_ei = 1;
        long long w = ((const long long*)ec)[i];
        if (w < 0 || w >= (1LL << 20)) bad_ec = 1;
    }
    if (bad_ei) atomicAnd(&g_ei64, 0);
    if (bad_ec) atomicAnd(&g_ec64, 0);
}

__global__ void k_minmax(const void* __restrict__ ec) {
    int is64 = g_ec64;
    int lmin = 0x7fffffff, lmax = (int)0x80000000;
    for (int e = blockIdx.x * blockDim.x + threadIdx.x; e < N_EDGES;
         e += gridDim.x * blockDim.x) {
        int v = (int)ld_int(ec, e, is64);
        lmin = min(lmin, v);
        lmax = max(lmax, v);
    }
    #pragma unroll
    for (int o = 16; o; o >>= 1) {
        lmin = min(lmin, __shfl_xor_sync(0xffffffffu, lmin, o));
        lmax = max(lmax, __shfl_xor_sync(0xffffffffu, lmax, o));
    }
    if ((threadIdx.x & 31) == 0) {
        atomicMin(&g_min, lmin);
        atomicMax(&g_max, lmax);
    }
}

__global__ void k_ew_deg(const void* __restrict__ ec,
                         const void* __restrict__ ei) {
    int e = blockIdx.x * blockDim.x + threadIdx.x;
    if (e >= N_EDGES) return;
    float mn = (float)g_min;
    float inv = 1.0f / ((float)g_max - mn);
    float w = ((float)(int)ld_int(ec, e, g_ec64) - mn) * inv;
    g_ew[e] = w;
    int c = (int)ld_int(ei, (long long)N_EDGES + e, g_ei64);
    if ((unsigned)c < (unsigned)N_NODES) atomicAdd(&g_deg[c], w);
}

__global__ void k_dinv() {
    int i = blockIdx.x * blockDim.x + threadIdx.x;
    if (i >= N_NODES) return;
    float d = g_deg[i];
    g_dinv[i] = d > 0.0f ? rsqrtf(d) : 0.0f;
}

__global__ void k_norm(const void* __restrict__ ei) {
    int e = blockIdx.x * blockDim.x + threadIdx.x;
    if (e >= N_EDGES) return;
    int is64 = g_ei64;
    int r = (int)ld_int(ei, e, is64);
    int c = (int)ld_int(ei, (long long)N_EDGES + e, is64);
    float nrm = 0.0f;
    if ((unsigned)r < (unsigned)N_NODES && (unsigned)c < (unsigned)N_NODES)
        nrm = g_dinv[r] * g_ew[e] * g_dinv[c];
    g_norm[e] = nrm;
}

// --------------------------------- GEMM -------------------------------------
// y = act(xin) @ W   (+ fused self-loop epilogue agg = y * dinv^2)
// LAYER 1: xin = x (external), K=256, no activation -> g_y1 / g_agg1
// LAYER 2: xin = relu(g_agg1 + b1), K=64           -> g_y2 / g_agg2
// 256 threads = 8 warps, 4 rows/warp -> 32 rows/block. N_NODES % 32 == 0.
template <int LAYER>
__global__ void k_gemm(const float* __restrict__ x_ext,
                       const float* __restrict__ W,
                       const float* __restrict__ bias) {
    constexpr int K  = (LAYER == 1) ? IN_DIM : HID_DIM;
    constexpr int KC = (LAYER == 1) ? 128 : 64;   // chunk rows of W
    __shared__ __align__(16) float2 sW[KC * 32];  // [KC][32] float2 (row-major W)

    int warp = threadIdx.x >> 5, lane = threadIdx.x & 31;
    int row0 = (blockIdx.x * 8 + warp) * 4;

    float xr[4][K / 32];
    #pragma unroll
    for (int r = 0; r < 4; r++) {
        #pragma unroll
        for (int j = 0; j < K / 32; j++) {
            float v;
            if (LAYER == 1) {
                v = x_ext[(row0 + r) * K + j * 32 + lane];
            } else {
                v = g_agg1[(row0 + r) * K + j * 32 + lane] + bias[j * 32 + lane];
                v = fmaxf(v, 0.0f);
            }
            xr[r][j] = v;
        }
    }

    float2 acc[4];
    #pragma unroll
    for (int r = 0; r < 4; r++) { acc[r].x = 0.0f; acc[r].y = 0.0f; }

    #pragma unroll
    for (int ch = 0; ch < K / KC; ch++) {
        // stage W rows [ch*KC, ch*KC+KC): contiguous 64-float rows == float2[32]
        {
            const float4* Wv = (const float4*)(W + ch * KC * 64);
            float4* sWv = (float4*)sW;
            for (int i = threadIdx.x; i < KC * 16; i += 256) sWv[i] = Wv[i];
        }
        __syncthreads();

        #pragma unroll
        for (int j = 0; j < KC / 32; j++) {
            int jj = ch * (KC / 32) + j;
            #pragma unroll 8
            for (int kk = 0; kk < 32; kk++) {
                float2 w = sW[(j * 32 + kk) * 32 + lane];
                #pragma unroll
                for (int r = 0; r < 4; r++) {
                    float xv = __shfl_sync(0xffffffffu, xr[r][jj], kk);
                    acc[r].x += xv * w.x;
                    acc[r].y += xv * w.y;
                }
            }
        }
        __syncthreads();
    }

    #pragma unroll
    for (int r = 0; r < 4; r++) {
        int row = row0 + r;
        float di = g_dinv[row];
        float s = di * di;
        float2 a = acc[r];
        float2 b2v; b2v.x = a.x * s; b2v.y = a.y * s;
        if constexpr (LAYER == 1) {
            ((float2*)g_y1)[row * 32 + lane] = a;
            ((float2*)g_agg1)[row * 32 + lane] = b2v;
        } else {
            ((float2*)g_y2)[row * 32 + lane] = a;
            ((float2*)g_agg2)[row * 32 + lane] = b2v;
        }
    }
}

// ------------------------------ edge scatter ---------------------------------
// warp per edge: gather y[row] (float2/lane), scale by norm, atomicAdd agg[col]
template <int LAYER>
__global__ void k_scatter(const void* __restrict__ ei) {
    int t = blockIdx.x * blockDim.x + threadIdx.x;
    int e = t >> 5;
    int lane = t & 31;
    if (e >= N_EDGES) return;
    int is64 = g_ei64;
    int r = (int)ld_int(ei, e, is64);
    int c = (int)ld_int(ei, (long long)N_EDGES + e, is64);
    if ((unsigned)r >= (unsigned)N_NODES || (unsigned)c >= (unsigned)N_NODES)
        return;
    float nrm = g_norm[e];
    float2 v;
    float* dst;
    if constexpr (LAYER == 1) {
        v = ((const float2*)g_y1)[r * 32 + lane];
        dst = g_agg1 + c * 64 + 2 * lane;
    } else {
        v = ((const float2*)g_y2)[r * 32 + lane];
        dst = g_agg2 + c * 64 + 2 * lane;
    }
    atomicAdd(dst,     v.x * nrm);
    atomicAdd(dst + 1, v.y * nrm);
}

// --------------------- finalize: bias2 + log_softmax -------------------------
__global__ void k_final(const float* __restrict__ b2, float* __restrict__ out,
                        int write_lsm) {
    int t = blockIdx.x * blockDim.x + threadIdx.x;
    int i = t >> 5;
    int lane = t & 31;
    if (i >= N_NODES) return;
    float2 v = ((const float2*)g_agg2)[i * 32 + lane];
    v.x += b2[2 * lane];
    v.y += b2[2 * lane + 1];
    ((float2*)out)[i * 32 + lane] = v;  // node_embeddings
    if (!write_lsm) return;
    float m = fmaxf(v.x, v.y);
    #pragma unroll
    for (int o = 16; o; o >>= 1) m = fmaxf(m, __shfl_xor_sync(0xffffffffu, m, o));
    float s = expf(v.x - m) + expf(v.y - m);
    #pragma unroll
    for (int o = 16; o; o >>= 1) s += __shfl_xor_sync(0xffffffffu, s, o);
    float lse = m + logf(s);
    float2 o2; o2.x = v.x - lse; o2.y = v.y - lse;
    ((float2*)(out + (size_t)N_NODES * OUT_DIM))[i * 32 + lane] = o2;
}

// --------------------------------- launch ------------------------------------
extern "C" void kernel_launch(void* const* d_in, const int* in_sizes, int n_in,
                              void* d_out, int out_size) {
    // Bind inputs by SIZE SIGNATURE, not position (order-agnostic):
    //   x          : 25,600,000 f32   edge_index : 3,200,000 ints
    //   edge_count :  1,600,000 ints  W1 : 16,384 f32   W2 : 4,096 f32
    //   b1, b2     : 64 f32 each (first 64-sized -> b1, second -> b2)
    const float* x = nullptr;
    const void *ei = nullptr, *ec = nullptr;
    const float *W1 = nullptr, *b1 = nullptr, *W2 = nullptr, *b2 = nullptr;
    for (int i = 0; i < n_in; i++) {
        int s = in_sizes[i];
        if (s == N_NODES * IN_DIM)       x  = (const float*)d_in[i];
        else if (s == 2 * N_EDGES)       ei = d_in[i];
        else if (s == N_EDGES)           ec = d_in[i];
        else if (s == IN_DIM * HID_DIM)  W1 = (const float*)d_in[i];
        else if (s == HID_DIM * OUT_DIM) W2 = (const float*)d_in[i];
        else if (s == HID_DIM) {
            if (!b1) b1 = (const float*)d_in[i];
            else     b2 = (const float*)d_in[i];
        }
    }
    float* out = (float*)d_out;
    if (!x || !ei || !ec || !W1 || !b1 || !W2 || !b2) return;

    int write_lsm = (out_size >= 2 * N_NODES * OUT_DIM) ? 1 : 0;

    k_init<<<(N_NODES + 255) / 256, 256>>>();
    k_detect<<<1, 256>>>(ei, ec);
    k_minmax<<<512, 256>>>(ec);
    k_ew_deg<<<(N_EDGES + 255) / 256, 256>>>(ec, ei);
    k_dinv<<<(N_NODES + 255) / 256, 256>>>();
    k_norm<<<(N_EDGES + 255) / 256, 256>>>(ei);

    // layer 1: y1 = x@W1 (+ agg1 = y1*dinv^2 self-loop), then edge scatter
    k_gemm<1><<<N_NODES / 32, 256>>>(x, W1, b1);
    k_scatter<1><<<(N_EDGES * 32 + 255) / 256, 256>>>(ei);

    // layer 2: y2 = relu(agg1+b1)@W2 (+ agg2 = y2*dinv^2), then edge scatter
    k_gemm<2><<<N_NODES / 32, 256>>>(x, W2, b1);
    k_scatter<2><<<(N_EDGES * 32 + 255) / 256, 256>>>(ei);

    // finalize: + b2 -> embeddings, log_softmax -> second half of d_out
    k_final<<<(N_NODES * 32 + 255) / 256, 256>>>(b2, out, write_lsm);
}

// round 7
// speedup vs baseline: 1.3824x; 1.3824x over previous
#include <cuda_runtime.h>
#include <cstdint>

#define N_NODES 100000
#define N_EDGES 1600000
#define IN_DIM  256
#define HID_DIM 64
#define OUT_DIM 64

// -------- scratch (device globals: allocation-free per harness rules) --------
__device__ __align__(16) float g_ew[N_EDGES];          // normalized edge weights
__device__ __align__(16) float g_norm[N_EDGES];        // dinv[row]*ew*dinv[col]
__device__ __align__(16) float g_deg[N_NODES];         // degree (init 1.0 self-loop)
__device__ __align__(16) float g_dinv[N_NODES];        // deg^{-1/2}
__device__ __align__(16) float g_y1[N_NODES * HID_DIM];    // x @ W1
__device__ __align__(16) float g_agg1[N_NODES * HID_DIM];  // layer-1 aggregation
__device__ __align__(16) float g_y2[N_NODES * OUT_DIM];    // h @ W2
__device__ __align__(16) float g_agg2[N_NODES * OUT_DIM];  // layer-2 aggregation
__device__ int g_min, g_max;
__device__ int g_ei64, g_ec64;   // 1 if buffer really is int64, 0 if int32

// flag-selected integer load (handles JAX silently demoting int64 -> int32)
__device__ __forceinline__ long long ld_int(const void* p, long long i, int is64) {
    if (is64) return ((const long long*)p)[i];
    return (long long)((const int*)p)[i];
}

// ------------------------------- prep kernels -------------------------------
__global__ void k_init() {
    int i = blockIdx.x * blockDim.x + threadIdx.x;
    if (i < N_NODES) g_deg[i] = 1.0f;               // self-loop weight 1
    if (i == 0) {
        g_min = 0x7fffffff; g_max = (int)0x80000000;
        g_ei64 = 1; g_ec64 = 1;
    }
}

// Probe dtype: if ANY of the first 4096 int64-interpreted values is out of
// plausible range, the buffer is int32.
__global__ void k_detect(const void* ei, const void* ec) {
    int bad_ei = 0, bad_ec = 0;
    for (int i = threadIdx.x; i < 4096; i += blockDim.x) {
        long long v = ((const long long*)ei)[i];
        if (v < 0 || v >= N_NODES) bad_ei = 1;
        long long w = ((const long long*)ec)[i];
        if (w < 0 || w >= (1LL << 20)) bad_ec = 1;
    }
    if (bad_ei) atomicAnd(&g_ei64, 0);
    if (bad_ec) atomicAnd(&g_ec64, 0);
}

__global__ void k_minmax(const void* __restrict__ ec) {
    int is64 = g_ec64;
    int lmin = 0x7fffffff, lmax = (int)0x80000000;
    for (int e = blockIdx.x * blockDim.x + threadIdx.x; e < N_EDGES;
         e += gridDim.x * blockDim.x) {
        int v = (int)ld_int(ec, e, is64);
        lmin = min(lmin, v);
        lmax = max(lmax, v);
    }
    #pragma unroll
    for (int o = 16; o; o >>= 1) {
        lmin = min(lmin, __shfl_xor_sync(0xffffffffu, lmin, o));
        lmax = max(lmax, __shfl_xor_sync(0xffffffffu, lmax, o));
    }
    if ((threadIdx.x & 31) == 0) {
        atomicMin(&g_min, lmin);
        atomicMax(&g_max, lmax);
    }
}

__global__ void k_ew_deg(const void* __restrict__ ec,
                         const void* __restrict__ ei) {
    int e = blockIdx.x * blockDim.x + threadIdx.x;
    if (e >= N_EDGES) return;
    float mn = (float)g_min;
    float inv = 1.0f / ((float)g_max - mn);
    float w = ((float)(int)ld_int(ec, e, g_ec64) - mn) * inv;
    g_ew[e] = w;
    int c = (int)ld_int(ei, (long long)N_EDGES + e, g_ei64);
    if ((unsigned)c < (unsigned)N_NODES) atomicAdd(&g_deg[c], w);
}

__global__ void k_dinv() {
    int i = blockIdx.x * blockDim.x + threadIdx.x;
    if (i >= N_NODES) return;
    float d = g_deg[i];
    g_dinv[i] = d > 0.0f ? rsqrtf(d) : 0.0f;
}

__global__ void k_norm(const void* __restrict__ ei) {
    int e = blockIdx.x * blockDim.x + threadIdx.x;
    if (e >= N_EDGES) return;
    int is64 = g_ei64;
    int r = (int)ld_int(ei, e, is64);
    int c = (int)ld_int(ei, (long long)N_EDGES + e, is64);
    float nrm = 0.0f;
    if ((unsigned)r < (unsigned)N_NODES && (unsigned)c < (unsigned)N_NODES)
        nrm = g_dinv[r] * g_ew[e] * g_dinv[c];
    g_norm[e] = nrm;
}

// --------------------------------- GEMM -------------------------------------
// y = act(xin) @ W   (+ fused self-loop epilogue agg = y * dinv^2)
// LAYER 1: xin = x (external), K=256, no activation -> g_y1 / g_agg1
// LAYER 2: xin = relu(g_agg1 + b1), K=64           -> g_y2 / g_agg2
template <int LAYER>
__global__ void k_gemm(const float* __restrict__ x_ext,
                       const float* __restrict__ W,
                       const float* __restrict__ bias) {
    constexpr int K  = (LAYER == 1) ? IN_DIM : HID_DIM;
    constexpr int KC = (LAYER == 1) ? 128 : 64;   // chunk rows of W
    __shared__ __align__(16) float2 sW[KC * 32];  // [KC][32] float2 (row-major W)

    int warp = threadIdx.x >> 5, lane = threadIdx.x & 31;
    int row0 = (blockIdx.x * 8 + warp) * 4;

    float xr[4][K / 32];
    #pragma unroll
    for (int r = 0; r < 4; r++) {
        #pragma unroll
        for (int j = 0; j < K / 32; j++) {
            float v;
            if (LAYER == 1) {
                v = x_ext[(row0 + r) * K + j * 32 + lane];
            } else {
                v = g_agg1[(row0 + r) * K + j * 32 + lane] + bias[j * 32 + lane];
                v = fmaxf(v, 0.0f);
            }
            xr[r][j] = v;
        }
    }

    float2 acc[4];
    #pragma unroll
    for (int r = 0; r < 4; r++) { acc[r].x = 0.0f; acc[r].y = 0.0f; }

    #pragma unroll
    for (int ch = 0; ch < K / KC; ch++) {
        {
            const float4* Wv = (const float4*)(W + ch * KC * 64);
            float4* sWv = (float4*)sW;
            for (int i = threadIdx.x; i < KC * 16; i += 256) sWv[i] = Wv[i];
        }
        __syncthreads();

        #pragma unroll
        for (int j = 0; j < KC / 32; j++) {
            int jj = ch * (KC / 32) + j;
            #pragma unroll 8
            for (int kk = 0; kk < 32; kk++) {
                float2 w = sW[(j * 32 + kk) * 32 + lane];
                #pragma unroll
                for (int r = 0; r < 4; r++) {
                    float xv = __shfl_sync(0xffffffffu, xr[r][jj], kk);
                    acc[r].x += xv * w.x;
                    acc[r].y += xv * w.y;
                }
            }
        }
        __syncthreads();
    }

    #pragma unroll
    for (int r = 0; r < 4; r++) {
        int row = row0 + r;
        float di = g_dinv[row];
        float s = di * di;
        float2 a = acc[r];
        float2 b2v; b2v.x = a.x * s; b2v.y = a.y * s;
        if constexpr (LAYER == 1) {
            ((float2*)g_y1)[row * 32 + lane] = a;
            ((float2*)g_agg1)[row * 32 + lane] = b2v;
        } else {
            ((float2*)g_y2)[row * 32 + lane] = a;
            ((float2*)g_agg2)[row * 32 + lane] = b2v;
        }
    }
}

// ------------------------------ edge scatter ---------------------------------
// 16 lanes per edge, float4 per lane: gather y[row], scale, ONE vector RED
// (atomicAdd float4) per lane -> 16 L2 atomic ops/edge instead of 64.
template <int LAYER>
__global__ void k_scatter(const void* __restrict__ ei) {
    int t = blockIdx.x * blockDim.x + threadIdx.x;
    int e = t >> 4;
    int l = t & 15;
    if (e >= N_EDGES) return;
    int is64 = g_ei64;
    int r = (int)ld_int(ei, e, is64);
    int c = (int)ld_int(ei, (long long)N_EDGES + e, is64);
    if ((unsigned)r >= (unsigned)N_NODES || (unsigned)c >= (unsigned)N_NODES)
        return;
    float nrm = g_norm[e];
    float4 v;
    float4* dst;
    if constexpr (LAYER == 1) {
        v = ((const float4*)g_y1)[r * 16 + l];
        dst = (float4*)(g_agg1 + c * 64 + 4 * l);
    } else {
        v = ((const float4*)g_y2)[r * 16 + l];
        dst = (float4*)(g_agg2 + c * 64 + 4 * l);
    }
    float4 s;
    s.x = v.x * nrm; s.y = v.y * nrm; s.z = v.z * nrm; s.w = v.w * nrm;
    atomicAdd(dst, s);   // sm_90+: single RED.E.ADD.v4.F32
}

// --------------------- finalize: bias2 + log_softmax -------------------------
__global__ void k_final(const float* __restrict__ b2, float* __restrict__ out,
                        int write_lsm) {
    int t = blockIdx.x * blockDim.x + threadIdx.x;
    int i = t >> 5;
    int lane = t & 31;
    if (i >= N_NODES) return;
    float2 v = ((const float2*)g_agg2)[i * 32 + lane];
    v.x += b2[2 * lane];
    v.y += b2[2 * lane + 1];
    ((float2*)out)[i * 32 + lane] = v;  // node_embeddings
    if (!write_lsm) return;
    float m = fmaxf(v.x, v.y);
    #pragma unroll
    for (int o = 16; o; o >>= 1) m = fmaxf(m, __shfl_xor_sync(0xffffffffu, m, o));
    float s = expf(v.x - m) + expf(v.y - m);
    #pragma unroll
    for (int o = 16; o; o >>= 1) s += __shfl_xor_sync(0xffffffffu, s, o);
    float lse = m + logf(s);
    float2 o2; o2.x = v.x - lse; o2.y = v.y - lse;
    ((float2*)(out + (size_t)N_NODES * OUT_DIM))[i * 32 + lane] = o2;
}

// --------------------------------- launch ------------------------------------
extern "C" void kernel_launch(void* const* d_in, const int* in_sizes, int n_in,
                              void* d_out, int out_size) {
    const float* x = nullptr;
    const void *ei = nullptr, *ec = nullptr;
    const float *W1 = nullptr, *b1 = nullptr, *W2 = nullptr, *b2 = nullptr;
    for (int i = 0; i < n_in; i++) {
        int s = in_sizes[i];
        if (s == N_NODES * IN_DIM)       x  = (const float*)d_in[i];
        else if (s == 2 * N_EDGES)       ei = d_in[i];
        else if (s == N_EDGES)           ec = d_in[i];
        else if (s == IN_DIM * HID_DIM)  W1 = (const float*)d_in[i];
        else if (s == HID_DIM * OUT_DIM) W2 = (const float*)d_in[i];
        else if (s == HID_DIM) {
            if (!b1) b1 = (const float*)d_in[i];
            else     b2 = (const float*)d_in[i];
        }
    }
    float* out = (float*)d_out;
    if (!x || !ei || !ec || !W1 || !b1 || !W2 || !b2) return;

    int write_lsm = (out_size >= 2 * N_NODES * OUT_DIM) ? 1 : 0;

    k_init<<<(N_NODES + 255) / 256, 256>>>();
    k_detect<<<1, 256>>>(ei, ec);
    k_minmax<<<512, 256>>>(ec);
    k_ew_deg<<<(N_EDGES + 255) / 256, 256>>>(ec, ei);
    k_dinv<<<(N_NODES + 255) / 256, 256>>>();
    k_norm<<<(N_EDGES + 255) / 256, 256>>>(ei);

    // layer 1: y1 = x@W1 (+ agg1 = y1*dinv^2 self-loop), then edge scatter
    k_gemm<1><<<N_NODES / 32, 256>>>(x, W1, b1);
    k_scatter<1><<<(N_EDGES * 16 + 255) / 256, 256>>>(ei);

    // layer 2: y2 = relu(agg1+b1)@W2 (+ agg2 = y2*dinv^2), then edge scatter
    k_gemm<2><<<N_NODES / 32, 256>>>(x, W2, b1);
    k_scatter<2><<<(N_EDGES * 16 + 255) / 256, 256>>>(ei);

    // finalize: + b2 -> embeddings, log_softmax -> second half of d_out
    k_final<<<(N_NODES * 32 + 255) / 256, 256>>>(b2, out, write_lsm);
}